// round 5
// baseline (speedup 1.0000x reference)
#include <cuda_runtime.h>
#include <math.h>
#include <stdint.h>

// Problem constants
#define BB 4
#define NN 16384
#define DD 64
#define HH 8

// scratch (static __device__ globals: allocation-free per harness rules)
__device__ float g_cs [BB * NN * 64];            // per token: cos[0..31], sin[0..31]
__device__ float g_kvp[BB * HH * 32 * 4096];     // per-(b,h,slab) partial kv
__device__ float g_MT [BB * HH * 4096];          // (kv @ Wo_h)/N, TRANSPOSED: [o][d]

__device__ __forceinline__ float4 ld4(const float* p) { return *reinterpret_cast<const float4*>(p); }
__device__ __forceinline__ void   st4(float* p, float4 v) { *reinterpret_cast<float4*>(p) = v; }
__device__ __forceinline__ ulonglong2 ld2u64(const float* p) {
    return *reinterpret_cast<const ulonglong2*>(p);
}

// packed dual-fp32 FMA: acc.{lo,hi} += a.{lo,hi} * b.{lo,hi}   (SASS FFMA2)
#define FMA2(acc, a, b) \
    asm("fma.rn.f32x2 %0, %1, %2, %0;" : "+l"(acc) : "l"(a), "l"(b))

__device__ __forceinline__ float unpack_sum(unsigned long long v) {
    unsigned int lo, hi;
    asm("mov.b64 {%0, %1}, %2;" : "=r"(lo), "=r"(hi) : "l"(v));
    return __uint_as_float(lo) + __uint_as_float(hi);
}

// ---------------------------------------------------------------------------
// K0: cos/sin table.  f_j = pos * 64 * 10000^(-j/32), j = 0..31
// ---------------------------------------------------------------------------
__global__ void cs_kernel(const float* __restrict__ pos) {
    int idx = blockIdx.x * blockDim.x + threadIdx.x;
    if (idx >= BB * NN * 32) return;
    int j = idx & 31;
    int n = idx >> 5;
    float t = pos[n] * 64.0f;
    float inv = expf(-0.28782313662425572f * (float)j);  // 10000^(-j/32)
    float f = t * inv;
    g_cs[n * 64 + j]      = cosf(f);
    g_cs[n * 64 + 32 + j] = sinf(f);
}

// ---------------------------------------------------------------------------
// K1: per-(b,h,slab) fused  kproj+vproj -> LN -> RoPE(k) -> kv partial
// Packed-f32x2 GEMMs, reduction-major smem layouts.
// smem: sWkT[o][i] + sWvT[o][i]; union {sXT[t][i] + sCS[t][*]} alias {sK[d][t] + sV[e][t]}
// ---------------------------------------------------------------------------
#define KV_SMEM_FLOATS (8704 + 8704)
__global__ __launch_bounds__(256, 2)
void kv_kernel(const float* __restrict__ x, const float* __restrict__ Wk,
               const float* __restrict__ Wv) {
    extern __shared__ float sm[];
    float* sWkT = sm;                   // [64][68] : (o, i)
    float* sWvT = sm + 4352;            // [64][68] : (o, i)
    float* sU   = sm + 8704;            // union region (8704 floats)
    float* sXT  = sU;                   // [64][68] : (t, i)
    float* sCS  = sU + 4352;            // [64][68] : (t, cos0..31 | sin0..31)
    float* sK   = sU;                   // [64][68] : (d, t)  ALIASED, live in P2
    float* sV   = sU + 4352;            // [64][68] : (e, t)  ALIASED, live in P2

    const int s = blockIdx.x, h = blockIdx.y, b = blockIdx.z;
    const int tid  = threadIdx.x;
    const int trow = tid >> 4, ocol = tid & 15;
    const int t0  = trow << 2;          // also d0 in P2
    const int oc4 = ocol << 2;          // also e0 in P2
    const int jb  = (ocol & 7) << 2;
    const float sgn = (ocol < 8) ? -1.0f : 1.0f;

    // stage weights transposed: sW*T[o][i]
    for (int idx = tid; idx < 4096; idx += 256) {
        int i = idx >> 6, o = idx & 63;
        int g = i * 512 + h * 64 + o;
        sWkT[o * 68 + i] = Wk[g];
        sWvT[o * 68 + i] = Wv[g];
    }

    unsigned long long kv2[4][4];
#pragma unroll
    for (int a = 0; a < 4; a++)
#pragma unroll
        for (int e = 0; e < 4; e++) kv2[a][e] = 0ull;

    for (int c = 0; c < 8; c++) {
        const size_t base = (size_t)b * NN + (size_t)s * 512 + (size_t)c * 64;

        // stage x (t-major) and cos/sin
        for (int idx = tid; idx < 4096; idx += 256) {
            int t = idx >> 6, i = idx & 63;
            sXT[t * 68 + i] = x[(base + t) * 64 + i];
            sCS[t * 68 + i] = g_cs[(base + t) * 64 + i];
        }
        __syncthreads();

        // P1: projection, packed over i
        unsigned long long ak2[4][4], av2[4][4];
#pragma unroll
        for (int a = 0; a < 4; a++)
#pragma unroll
            for (int e = 0; e < 4; e++) { ak2[a][e] = 0ull; av2[a][e] = 0ull; }

#pragma unroll 4
        for (int i4 = 0; i4 < 64; i4 += 4) {
            ulonglong2 xq[4], kq[4], vq[4];
#pragma unroll
            for (int tt = 0; tt < 4; tt++) xq[tt] = ld2u64(&sXT[(t0 + tt) * 68 + i4]);
#pragma unroll
            for (int j = 0; j < 4; j++) {
                kq[j] = ld2u64(&sWkT[(oc4 + j) * 68 + i4]);
                vq[j] = ld2u64(&sWvT[(oc4 + j) * 68 + i4]);
            }
#pragma unroll
            for (int tt = 0; tt < 4; tt++)
#pragma unroll
                for (int j = 0; j < 4; j++) {
                    FMA2(ak2[tt][j], xq[tt].x, kq[j].x);
                    FMA2(ak2[tt][j], xq[tt].y, kq[j].y);
                    FMA2(av2[tt][j], xq[tt].x, vq[j].x);
                    FMA2(av2[tt][j], xq[tt].y, vq[j].y);
                }
        }

        float ak[4][4], av[4][4];
#pragma unroll
        for (int tt = 0; tt < 4; tt++)
#pragma unroll
            for (int j = 0; j < 4; j++) {
                ak[tt][j] = unpack_sum(ak2[tt][j]);
                av[tt][j] = unpack_sum(av2[tt][j]);
            }

        // LN(k,v) + RoPE(k); ak := k_rot, av := v_ln (in registers)
        const float inv64 = 1.0f / 64.0f;
#pragma unroll
        for (int tt = 0; tt < 4; tt++) {
            float sk = ak[tt][0] + ak[tt][1] + ak[tt][2] + ak[tt][3];
            float sk2 = ak[tt][0]*ak[tt][0] + ak[tt][1]*ak[tt][1] + ak[tt][2]*ak[tt][2] + ak[tt][3]*ak[tt][3];
            float sv = av[tt][0] + av[tt][1] + av[tt][2] + av[tt][3];
            float sv2 = av[tt][0]*av[tt][0] + av[tt][1]*av[tt][1] + av[tt][2]*av[tt][2] + av[tt][3]*av[tt][3];
#pragma unroll
            for (int m = 1; m <= 8; m <<= 1) {
                sk  += __shfl_xor_sync(0xffffffffu, sk,  m);
                sk2 += __shfl_xor_sync(0xffffffffu, sk2, m);
                sv  += __shfl_xor_sync(0xffffffffu, sv,  m);
                sv2 += __shfl_xor_sync(0xffffffffu, sv2, m);
            }
            float mk = sk * inv64;
            float vk = fmaxf(sk2 * inv64 - mk * mk, 0.0f);
            float rk = rsqrtf(vk + 1e-5f);
            float mv = sv * inv64;
            float vv = fmaxf(sv2 * inv64 - mv * mv, 0.0f);
            float rv = rsqrtf(vv + 1e-5f);

            float kn[4];
#pragma unroll
            for (int j = 0; j < 4; j++) {
                kn[j]     = (ak[tt][j] - mk) * rk;
                av[tt][j] = (av[tt][j] - mv) * rv;
            }
            float pk[4];
#pragma unroll
            for (int j = 0; j < 4; j++)
                pk[j] = __shfl_xor_sync(0xffffffffu, kn[j], 8);  // partner dim d^32

            int t = t0 + tt;
            float4 cq = ld4(&sCS[t * 68 + jb]);
            float4 sq = ld4(&sCS[t * 68 + 32 + jb]);
            float cs[4] = {cq.x, cq.y, cq.z, cq.w};
            float ss[4] = {sq.x, sq.y, sq.z, sq.w};
#pragma unroll
            for (int j = 0; j < 4; j++)
                ak[tt][j] = kn[j] * cs[j] + sgn * pk[j] * ss[j];
        }
        __syncthreads();   // sXT/sCS reads done before aliased sK/sV writes

        // write k_rot, v_ln transposed: sK[d][t], sV[e][t]
#pragma unroll
        for (int j = 0; j < 4; j++) {
            st4(&sK[(oc4 + j) * 68 + t0], make_float4(ak[0][j], ak[1][j], ak[2][j], ak[3][j]));
            st4(&sV[(oc4 + j) * 68 + t0], make_float4(av[0][j], av[1][j], av[2][j], av[3][j]));
        }
        __syncthreads();

        // P2: kv[d][e] += sum_t k_rot[d][t] * v[e][t], packed over t
#pragma unroll 4
        for (int t4 = 0; t4 < 64; t4 += 4) {
            ulonglong2 kq[4], vq[4];
#pragma unroll
            for (int a = 0; a < 4; a++) kq[a] = ld2u64(&sK[(t0 + a) * 68 + t4]);
#pragma unroll
            for (int e = 0; e < 4; e++) vq[e] = ld2u64(&sV[(oc4 + e) * 68 + t4]);
#pragma unroll
            for (int a = 0; a < 4; a++)
#pragma unroll
                for (int e = 0; e < 4; e++) {
                    FMA2(kv2[a][e], kq[a].x, vq[e].x);
                    FMA2(kv2[a][e], kq[a].y, vq[e].y);
                }
        }
        __syncthreads();   // P2 reads done before next chunk's aliased staging
    }

    float* dst = g_kvp + ((((size_t)b * HH + h) * 32 + s) << 12);
#pragma unroll
    for (int a = 0; a < 4; a++)
        st4(&dst[(t0 + a) * 64 + oc4],
            make_float4(unpack_sum(kv2[a][0]), unpack_sum(kv2[a][1]),
                        unpack_sum(kv2[a][2]), unpack_sum(kv2[a][3])));
}

// ---------------------------------------------------------------------------
// K2: reduce 32 slabs -> kv[b,h];  M = kv @ Wo_h / N, stored TRANSPOSED [o][d]
// ---------------------------------------------------------------------------
__global__ void m_kernel(const float* __restrict__ Wo) {
    __shared__ float sKv[64 * 68];
    __shared__ float sWo[64 * 68];
    const int h = blockIdx.x, b = blockIdx.y;
    const int tid = threadIdx.x;

    const float* p0 = g_kvp + (((size_t)b * HH + h) * 32 << 12);
    for (int idx = tid; idx < 4096; idx += 256) {
        float acc = 0.0f;
#pragma unroll 8
        for (int s = 0; s < 32; s++) acc += p0[(size_t)s * 4096 + idx];
        int d = idx >> 6, e = idx & 63;
        sKv[d * 68 + e] = acc;
        sWo[d * 68 + e] = Wo[(h * 64 + d) * 64 + e];
    }
    __syncthreads();

    const int d0 = (tid >> 4) << 2, o0 = (tid & 15) << 2;
    float m[4][4];
#pragma unroll
    for (int a = 0; a < 4; a++)
#pragma unroll
        for (int e = 0; e < 4; e++) m[a][e] = 0.0f;

#pragma unroll 4
    for (int e = 0; e < 64; e++) {
        float kd[4];
#pragma unroll
        for (int a = 0; a < 4; a++) kd[a] = sKv[(d0 + a) * 68 + e];
        float4 wq = ld4(&sWo[e * 68 + o0]);
        float wo[4] = {wq.x, wq.y, wq.z, wq.w};
#pragma unroll
        for (int a = 0; a < 4; a++)
#pragma unroll
            for (int j = 0; j < 4; j++) m[a][j] = fmaf(kd[a], wo[j], m[a][j]);
    }

    const float scale = 1.0f / (float)NN;
    float* dst = g_MT + ((size_t)b * HH + h) * 4096;
#pragma unroll
    for (int j = 0; j < 4; j++)   // transposed: row = o, col = d
        st4(&dst[(o0 + j) * 64 + d0],
            make_float4(m[0][j] * scale, m[1][j] * scale, m[2][j] * scale, m[3][j] * scale));
}

// ---------------------------------------------------------------------------
// K3: out[b,n] = sum_h RoPE(x Wq_h) @ M[b,h]   (packed f32x2)
// smem: sA union {sWqT[o][i] | sUfin[t][r]} + sMT[o][d] + sXT[t][i] + sCS[t][*]
// ---------------------------------------------------------------------------
#define OUT_SMEM_FLOATS (4352 * 4)
__global__ __launch_bounds__(256, 2)
void out_kernel(const float* __restrict__ x, const float* __restrict__ Wq,
                float* __restrict__ out) {
    extern __shared__ float sm[];
    float* sA   = sm;                   // [64][68] union: Wq^T (o,i)  then  U (t,r)
    float* sMT  = sm + 4352;            // [64][68] : (o, d)
    float* sXT  = sm + 8704;            // [64][68] : (t, i)
    float* sCS  = sm + 13056;           // [64][68]

    const int chunk = blockIdx.x, b = blockIdx.y;
    const int tid  = threadIdx.x;
    const int trow = tid >> 4, ocol = tid & 15;
    const int t0  = trow << 2;
    const int oc4 = ocol << 2;
    const int jb  = (ocol & 7) << 2;
    const float sgn = (ocol < 8) ? -1.0f : 1.0f;
    const size_t base = (size_t)b * NN + (size_t)chunk * 64;

    for (int idx = tid; idx < 4096; idx += 256) {
        int t = idx >> 6, i = idx & 63;
        sXT[t * 68 + i] = x[(base + t) * 64 + i];
        sCS[t * 68 + i] = g_cs[(base + t) * 64 + i];
    }

    unsigned long long oacc2[4][4];
#pragma unroll
    for (int a = 0; a < 4; a++)
#pragma unroll
        for (int e = 0; e < 4; e++) oacc2[a][e] = 0ull;

    for (int h = 0; h < HH; h++) {
        __syncthreads();   // prior iter's sA/sMT readers done before overwrite
        for (int idx = tid; idx < 4096; idx += 256) {
            int i = idx >> 6, o = idx & 63;
            sA[o * 68 + i] = Wq[i * 512 + h * 64 + o];          // Wq^T (o,i)
        }
        for (int idx = tid; idx < 4096; idx += 256) {
            int o = idx >> 6, d = idx & 63;
            sMT[o * 68 + d] = g_MT[(((size_t)b * HH + h) * 64 + o) * 64 + d];
        }
        __syncthreads();

        // q projection, packed over i
        unsigned long long ua2[4][4];
#pragma unroll
        for (int a = 0; a < 4; a++)
#pragma unroll
            for (int e = 0; e < 4; e++) ua2[a][e] = 0ull;

#pragma unroll 4
        for (int i4 = 0; i4 < 64; i4 += 4) {
            ulonglong2 xq[4], wq[4];
#pragma unroll
            for (int tt = 0; tt < 4; tt++) xq[tt] = ld2u64(&sXT[(t0 + tt) * 68 + i4]);
#pragma unroll
            for (int j = 0; j < 4; j++) wq[j] = ld2u64(&sA[(oc4 + j) * 68 + i4]);
#pragma unroll
            for (int tt = 0; tt < 4; tt++)
#pragma unroll
                for (int j = 0; j < 4; j++) {
                    FMA2(ua2[tt][j], xq[tt].x, wq[j].x);
                    FMA2(ua2[tt][j], xq[tt].y, wq[j].y);
                }
        }

        float ua[4][4];
#pragma unroll
        for (int tt = 0; tt < 4; tt++)
#pragma unroll
            for (int j = 0; j < 4; j++) ua[tt][j] = unpack_sum(ua2[tt][j]);

        // RoPE (in registers)
#pragma unroll
        for (int tt = 0; tt < 4; tt++) {
            int t = t0 + tt;
            float4 cq = ld4(&sCS[t * 68 + jb]);
            float4 sq = ld4(&sCS[t * 68 + 32 + jb]);
            float cs[4] = {cq.x, cq.y, cq.z, cq.w};
            float ss[4] = {sq.x, sq.y, sq.z, sq.w};
            float pa[4];
#pragma unroll
            for (int j = 0; j < 4; j++)
                pa[j] = __shfl_xor_sync(0xffffffffu, ua[tt][j], 8);
#pragma unroll
            for (int j = 0; j < 4; j++)
                ua[tt][j] = ua[tt][j] * cs[j] + sgn * pa[j] * ss[j];
        }
        __syncthreads();   // all Wq^T reads done before aliased U writes

        // write rotated q natural-major: sUfin[t][r]
#pragma unroll
        for (int tt = 0; tt < 4; tt++)
            st4(&sA[(t0 + tt) * 68 + oc4],
                make_float4(ua[tt][0], ua[tt][1], ua[tt][2], ua[tt][3]));
        __syncthreads();

        // out[t][o] += sum_r U[t][r] * MT[o][r], packed over r
#pragma unroll 4
        for (int r4 = 0; r4 < 64; r4 += 4) {
            ulonglong2 uq[4], mq[4];
#pragma unroll
            for (int tt = 0; tt < 4; tt++) uq[tt] = ld2u64(&sA[(t0 + tt) * 68 + r4]);
#pragma unroll
            for (int j = 0; j < 4; j++)  mq[j]  = ld2u64(&sMT[(oc4 + j) * 68 + r4]);
#pragma unroll
            for (int tt = 0; tt < 4; tt++)
#pragma unroll
                for (int j = 0; j < 4; j++) {
                    FMA2(oacc2[tt][j], uq[tt].x, mq[j].x);
                    FMA2(oacc2[tt][j], uq[tt].y, mq[j].y);
                }
        }
    }

#pragma unroll
    for (int tt = 0; tt < 4; tt++)
        st4(&out[(base + t0 + tt) * 64 + oc4],
            make_float4(unpack_sum(oacc2[tt][0]), unpack_sum(oacc2[tt][1]),
                        unpack_sum(oacc2[tt][2]), unpack_sum(oacc2[tt][3])));
}

// ---------------------------------------------------------------------------
extern "C" void kernel_launch(void* const* d_in, const int* in_sizes, int n_in,
                              void* d_out, int out_size) {
    const float* x   = (const float*)d_in[0];
    const float* pos = (const float*)d_in[1];
    const float* Wq  = (const float*)d_in[2];
    const float* Wk  = (const float*)d_in[3];
    const float* Wv  = (const float*)d_in[4];
    const float* Wo  = (const float*)d_in[5];
    float* out = (float*)d_out;

    cudaFuncSetAttribute(kv_kernel,  cudaFuncAttributeMaxDynamicSharedMemorySize,
                         KV_SMEM_FLOATS * (int)sizeof(float));
    cudaFuncSetAttribute(out_kernel, cudaFuncAttributeMaxDynamicSharedMemorySize,
                         OUT_SMEM_FLOATS * (int)sizeof(float));

    cs_kernel<<<(BB * NN * 32 + 255) / 256, 256>>>(pos);
    kv_kernel<<<dim3(32, HH, BB), 256, KV_SMEM_FLOATS * sizeof(float)>>>(x, Wk, Wv);
    m_kernel<<<dim3(HH, BB), 256>>>(Wo);
    out_kernel<<<dim3(NN / 64, BB), 256, OUT_SMEM_FLOATS * sizeof(float)>>>(x, Wq, out);
}

// round 9
// speedup vs baseline: 1.0016x; 1.0016x over previous
#include <cuda_runtime.h>
#include <math.h>
#include <stdint.h>

// Problem constants
#define BB 4
#define NN 16384
#define DD 64
#define HH 8

// scratch (static __device__ globals: allocation-free per harness rules)
__device__ float g_cs [BB * NN * 64];            // per token: cos[0..31], sin[0..31]
__device__ float g_kvp[BB * HH * 32 * 4096];     // per-(b,h,slab) partial kv
__device__ float g_MT [BB * HH * 4096];          // (kv @ Wo_h)/N, TRANSPOSED: [o][d]

__device__ __forceinline__ float4 ld4(const float* p) { return *reinterpret_cast<const float4*>(p); }
__device__ __forceinline__ void   st4(float* p, float4 v) { *reinterpret_cast<float4*>(p) = v; }
__device__ __forceinline__ ulonglong2 ld2u64(const float* p) {
    return *reinterpret_cast<const ulonglong2*>(p);
}

// packed dual-fp32 FMA: acc.{lo,hi} += a.{lo,hi} * b.{lo,hi}   (SASS FFMA2)
#define FMA2(acc, a, b) \
    asm("fma.rn.f32x2 %0, %1, %2, %0;" : "+l"(acc) : "l"(a), "l"(b))

__device__ __forceinline__ float unpack_sum(unsigned long long v) {
    unsigned int lo, hi;
    asm("mov.b64 {%0, %1}, %2;" : "=r"(lo), "=r"(hi) : "l"(v));
    return __uint_as_float(lo) + __uint_as_float(hi);
}

// ---------------------------------------------------------------------------
// K0: cos/sin table.  f_j = pos * 64 * 10000^(-j/32), j = 0..31
// ---------------------------------------------------------------------------
__global__ void cs_kernel(const float* __restrict__ pos) {
    int idx = blockIdx.x * blockDim.x + threadIdx.x;
    if (idx >= BB * NN * 32) return;
    int j = idx & 31;
    int n = idx >> 5;
    float t = pos[n] * 64.0f;
    float inv = expf(-0.28782313662425572f * (float)j);  // 10000^(-j/32)
    float f = t * inv;
    g_cs[n * 64 + j]      = cosf(f);
    g_cs[n * 64 + 32 + j] = sinf(f);
}

// ---------------------------------------------------------------------------
// K1: per-(b,h,slab) fused  kproj+vproj -> LN -> RoPE(k) -> kv partial
// Packed-f32x2 GEMMs, reduction-major smem layouts.
// smem: sWkT[o][i] + sWvT[o][i]; union {sXT[t][i] + sCS[t][*]} alias {sK[d][t] + sV[e][t]}
// ---------------------------------------------------------------------------
#define KV_SMEM_FLOATS (8704 + 8704)
__global__ __launch_bounds__(256, 2)
void kv_kernel(const float* __restrict__ x, const float* __restrict__ Wk,
               const float* __restrict__ Wv) {
    extern __shared__ float sm[];
    float* sWkT = sm;                   // [64][68] : (o, i)
    float* sWvT = sm + 4352;            // [64][68] : (o, i)
    float* sU   = sm + 8704;            // union region (8704 floats)
    float* sXT  = sU;                   // [64][68] : (t, i)
    float* sCS  = sU + 4352;            // [64][68] : (t, cos0..31 | sin0..31)
    float* sK   = sU;                   // [64][68] : (d, t)  ALIASED, live in P2
    float* sV   = sU + 4352;            // [64][68] : (e, t)  ALIASED, live in P2

    const int s = blockIdx.x, h = blockIdx.y, b = blockIdx.z;
    const int tid  = threadIdx.x;
    const int trow = tid >> 4, ocol = tid & 15;
    const int t0  = trow << 2;          // also d0 in P2
    const int oc4 = ocol << 2;          // also e0 in P2
    const int jb  = (ocol & 7) << 2;
    const float sgn = (ocol < 8) ? -1.0f : 1.0f;

    // stage weights transposed: sW*T[o][i]
    for (int idx = tid; idx < 4096; idx += 256) {
        int i = idx >> 6, o = idx & 63;
        int g = i * 512 + h * 64 + o;
        sWkT[o * 68 + i] = Wk[g];
        sWvT[o * 68 + i] = Wv[g];
    }

    unsigned long long kv2[4][4];
#pragma unroll
    for (int a = 0; a < 4; a++)
#pragma unroll
        for (int e = 0; e < 4; e++) kv2[a][e] = 0ull;

    for (int c = 0; c < 8; c++) {
        const size_t base = (size_t)b * NN + (size_t)s * 512 + (size_t)c * 64;

        // stage x (t-major) and cos/sin
        for (int idx = tid; idx < 4096; idx += 256) {
            int t = idx >> 6, i = idx & 63;
            sXT[t * 68 + i] = x[(base + t) * 64 + i];
            sCS[t * 68 + i] = g_cs[(base + t) * 64 + i];
        }
        __syncthreads();

        // P1: projection, packed over i
        unsigned long long ak2[4][4], av2[4][4];
#pragma unroll
        for (int a = 0; a < 4; a++)
#pragma unroll
            for (int e = 0; e < 4; e++) { ak2[a][e] = 0ull; av2[a][e] = 0ull; }

#pragma unroll 4
        for (int i4 = 0; i4 < 64; i4 += 4) {
            ulonglong2 xq[4], kq[4], vq[4];
#pragma unroll
            for (int tt = 0; tt < 4; tt++) xq[tt] = ld2u64(&sXT[(t0 + tt) * 68 + i4]);
#pragma unroll
            for (int j = 0; j < 4; j++) {
                kq[j] = ld2u64(&sWkT[(oc4 + j) * 68 + i4]);
                vq[j] = ld2u64(&sWvT[(oc4 + j) * 68 + i4]);
            }
#pragma unroll
            for (int tt = 0; tt < 4; tt++)
#pragma unroll
                for (int j = 0; j < 4; j++) {
                    FMA2(ak2[tt][j], xq[tt].x, kq[j].x);
                    FMA2(ak2[tt][j], xq[tt].y, kq[j].y);
                    FMA2(av2[tt][j], xq[tt].x, vq[j].x);
                    FMA2(av2[tt][j], xq[tt].y, vq[j].y);
                }
        }

        float ak[4][4], av[4][4];
#pragma unroll
        for (int tt = 0; tt < 4; tt++)
#pragma unroll
            for (int j = 0; j < 4; j++) {
                ak[tt][j] = unpack_sum(ak2[tt][j]);
                av[tt][j] = unpack_sum(av2[tt][j]);
            }

        // LN(k,v) + RoPE(k); ak := k_rot, av := v_ln (in registers)
        const float inv64 = 1.0f / 64.0f;
#pragma unroll
        for (int tt = 0; tt < 4; tt++) {
            float sk = ak[tt][0] + ak[tt][1] + ak[tt][2] + ak[tt][3];
            float sk2 = ak[tt][0]*ak[tt][0] + ak[tt][1]*ak[tt][1] + ak[tt][2]*ak[tt][2] + ak[tt][3]*ak[tt][3];
            float sv = av[tt][0] + av[tt][1] + av[tt][2] + av[tt][3];
            float sv2 = av[tt][0]*av[tt][0] + av[tt][1]*av[tt][1] + av[tt][2]*av[tt][2] + av[tt][3]*av[tt][3];
#pragma unroll
            for (int m = 1; m <= 8; m <<= 1) {
                sk  += __shfl_xor_sync(0xffffffffu, sk,  m);
                sk2 += __shfl_xor_sync(0xffffffffu, sk2, m);
                sv  += __shfl_xor_sync(0xffffffffu, sv,  m);
                sv2 += __shfl_xor_sync(0xffffffffu, sv2, m);
            }
            float mk = sk * inv64;
            float vk = fmaxf(sk2 * inv64 - mk * mk, 0.0f);
            float rk = rsqrtf(vk + 1e-5f);
            float mv = sv * inv64;
            float vv = fmaxf(sv2 * inv64 - mv * mv, 0.0f);
            float rv = rsqrtf(vv + 1e-5f);

            float kn[4];
#pragma unroll
            for (int j = 0; j < 4; j++) {
                kn[j]     = (ak[tt][j] - mk) * rk;
                av[tt][j] = (av[tt][j] - mv) * rv;
            }
            float pk[4];
#pragma unroll
            for (int j = 0; j < 4; j++)
                pk[j] = __shfl_xor_sync(0xffffffffu, kn[j], 8);  // partner dim d^32

            int t = t0 + tt;
            float4 cq = ld4(&sCS[t * 68 + jb]);
            float4 sq = ld4(&sCS[t * 68 + 32 + jb]);
            float cs[4] = {cq.x, cq.y, cq.z, cq.w};
            float ss[4] = {sq.x, sq.y, sq.z, sq.w};
#pragma unroll
            for (int j = 0; j < 4; j++)
                ak[tt][j] = kn[j] * cs[j] + sgn * pk[j] * ss[j];
        }
        __syncthreads();   // sXT/sCS reads done before aliased sK/sV writes

        // write k_rot, v_ln transposed: sK[d][t], sV[e][t]
#pragma unroll
        for (int j = 0; j < 4; j++) {
            st4(&sK[(oc4 + j) * 68 + t0], make_float4(ak[0][j], ak[1][j], ak[2][j], ak[3][j]));
            st4(&sV[(oc4 + j) * 68 + t0], make_float4(av[0][j], av[1][j], av[2][j], av[3][j]));
        }
        __syncthreads();

        // P2: kv[d][e] += sum_t k_rot[d][t] * v[e][t], packed over t
#pragma unroll 4
        for (int t4 = 0; t4 < 64; t4 += 4) {
            ulonglong2 kq[4], vq[4];
#pragma unroll
            for (int a = 0; a < 4; a++) kq[a] = ld2u64(&sK[(t0 + a) * 68 + t4]);
#pragma unroll
            for (int e = 0; e < 4; e++) vq[e] = ld2u64(&sV[(oc4 + e) * 68 + t4]);
#pragma unroll
            for (int a = 0; a < 4; a++)
#pragma unroll
                for (int e = 0; e < 4; e++) {
                    FMA2(kv2[a][e], kq[a].x, vq[e].x);
                    FMA2(kv2[a][e], kq[a].y, vq[e].y);
                }
        }
        __syncthreads();   // P2 reads done before next chunk's aliased staging
    }

    float* dst = g_kvp + ((((size_t)b * HH + h) * 32 + s) << 12);
#pragma unroll
    for (int a = 0; a < 4; a++)
        st4(&dst[(t0 + a) * 64 + oc4],
            make_float4(unpack_sum(kv2[a][0]), unpack_sum(kv2[a][1]),
                        unpack_sum(kv2[a][2]), unpack_sum(kv2[a][3])));
}

// ---------------------------------------------------------------------------
// K2: reduce 32 slabs -> kv[b,h];  M = kv @ Wo_h / N, stored TRANSPOSED [o][d]
// ---------------------------------------------------------------------------
__global__ void m_kernel(const float* __restrict__ Wo) {
    __shared__ float sKv[64 * 68];
    __shared__ float sWo[64 * 68];
    const int h = blockIdx.x, b = blockIdx.y;
    const int tid = threadIdx.x;

    const float* p0 = g_kvp + (((size_t)b * HH + h) * 32 << 12);
    for (int idx = tid; idx < 4096; idx += 256) {
        float acc = 0.0f;
#pragma unroll 8
        for (int s = 0; s < 32; s++) acc += p0[(size_t)s * 4096 + idx];
        int d = idx >> 6, e = idx & 63;
        sKv[d * 68 + e] = acc;
        sWo[d * 68 + e] = Wo[(h * 64 + d) * 64 + e];
    }
    __syncthreads();

    const int d0 = (tid >> 4) << 2, o0 = (tid & 15) << 2;
    float m[4][4];
#pragma unroll
    for (int a = 0; a < 4; a++)
#pragma unroll
        for (int e = 0; e < 4; e++) m[a][e] = 0.0f;

#pragma unroll 4
    for (int e = 0; e < 64; e++) {
        float kd[4];
#pragma unroll
        for (int a = 0; a < 4; a++) kd[a] = sKv[(d0 + a) * 68 + e];
        float4 wq = ld4(&sWo[e * 68 + o0]);
        float wo[4] = {wq.x, wq.y, wq.z, wq.w};
#pragma unroll
        for (int a = 0; a < 4; a++)
#pragma unroll
            for (int j = 0; j < 4; j++) m[a][j] = fmaf(kd[a], wo[j], m[a][j]);
    }

    const float scale = 1.0f / (float)NN;
    float* dst = g_MT + ((size_t)b * HH + h) * 4096;
#pragma unroll
    for (int j = 0; j < 4; j++)   // transposed: row = o, col = d
        st4(&dst[(o0 + j) * 64 + d0],
            make_float4(m[0][j] * scale, m[1][j] * scale, m[2][j] * scale, m[3][j] * scale));
}

// ---------------------------------------------------------------------------
// K3: out[b,n] = sum_h RoPE(x Wq_h) @ M[b,h]   (packed f32x2)
// smem: sA union {sWqT[o][i] | sUfin[t][r]} + sMT[o][d] + sXT[t][i] + sCS[t][*]
// ---------------------------------------------------------------------------
#define OUT_SMEM_FLOATS (4352 * 4)
__global__ __launch_bounds__(256, 2)
void out_kernel(const float* __restrict__ x, const float* __restrict__ Wq,
                float* __restrict__ out) {
    extern __shared__ float sm[];
    float* sA   = sm;                   // [64][68] union: Wq^T (o,i)  then  U (t,r)
    float* sMT  = sm + 4352;            // [64][68] : (o, d)
    float* sXT  = sm + 8704;            // [64][68] : (t, i)
    float* sCS  = sm + 13056;           // [64][68]

    const int chunk = blockIdx.x, b = blockIdx.y;
    const int tid  = threadIdx.x;
    const int trow = tid >> 4, ocol = tid & 15;
    const int t0  = trow << 2;
    const int oc4 = ocol << 2;
    const int jb  = (ocol & 7) << 2;
    const float sgn = (ocol < 8) ? -1.0f : 1.0f;
    const size_t base = (size_t)b * NN + (size_t)chunk * 64;

    for (int idx = tid; idx < 4096; idx += 256) {
        int t = idx >> 6, i = idx & 63;
        sXT[t * 68 + i] = x[(base + t) * 64 + i];
        sCS[t * 68 + i] = g_cs[(base + t) * 64 + i];
    }

    unsigned long long oacc2[4][4];
#pragma unroll
    for (int a = 0; a < 4; a++)
#pragma unroll
        for (int e = 0; e < 4; e++) oacc2[a][e] = 0ull;

    for (int h = 0; h < HH; h++) {
        __syncthreads();   // prior iter's sA/sMT readers done before overwrite
        for (int idx = tid; idx < 4096; idx += 256) {
            int i = idx >> 6, o = idx & 63;
            sA[o * 68 + i] = Wq[i * 512 + h * 64 + o];          // Wq^T (o,i)
        }
        for (int idx = tid; idx < 4096; idx += 256) {
            int o = idx >> 6, d = idx & 63;
            sMT[o * 68 + d] = g_MT[(((size_t)b * HH + h) * 64 + o) * 64 + d];
        }
        __syncthreads();

        // q projection, packed over i
        unsigned long long ua2[4][4];
#pragma unroll
        for (int a = 0; a < 4; a++)
#pragma unroll
            for (int e = 0; e < 4; e++) ua2[a][e] = 0ull;

#pragma unroll 4
        for (int i4 = 0; i4 < 64; i4 += 4) {
            ulonglong2 xq[4], wq[4];
#pragma unroll
            for (int tt = 0; tt < 4; tt++) xq[tt] = ld2u64(&sXT[(t0 + tt) * 68 + i4]);
#pragma unroll
            for (int j = 0; j < 4; j++) wq[j] = ld2u64(&sA[(oc4 + j) * 68 + i4]);
#pragma unroll
            for (int tt = 0; tt < 4; tt++)
#pragma unroll
                for (int j = 0; j < 4; j++) {
                    FMA2(ua2[tt][j], xq[tt].x, wq[j].x);
                    FMA2(ua2[tt][j], xq[tt].y, wq[j].y);
                }
        }

        float ua[4][4];
#pragma unroll
        for (int tt = 0; tt < 4; tt++)
#pragma unroll
            for (int j = 0; j < 4; j++) ua[tt][j] = unpack_sum(ua2[tt][j]);

        // RoPE (in registers)
#pragma unroll
        for (int tt = 0; tt < 4; tt++) {
            int t = t0 + tt;
            float4 cq = ld4(&sCS[t * 68 + jb]);
            float4 sq = ld4(&sCS[t * 68 + 32 + jb]);
            float cs[4] = {cq.x, cq.y, cq.z, cq.w};
            float ss[4] = {sq.x, sq.y, sq.z, sq.w};
            float pa[4];
#pragma unroll
            for (int j = 0; j < 4; j++)
                pa[j] = __shfl_xor_sync(0xffffffffu, ua[tt][j], 8);
#pragma unroll
            for (int j = 0; j < 4; j++)
                ua[tt][j] = ua[tt][j] * cs[j] + sgn * pa[j] * ss[j];
        }
        __syncthreads();   // all Wq^T reads done before aliased U writes

        // write rotated q natural-major: sUfin[t][r]
#pragma unroll
        for (int tt = 0; tt < 4; tt++)
            st4(&sA[(t0 + tt) * 68 + oc4],
                make_float4(ua[tt][0], ua[tt][1], ua[tt][2], ua[tt][3]));
        __syncthreads();

        // out[t][o] += sum_r U[t][r] * MT[o][r], packed over r
#pragma unroll 4
        for (int r4 = 0; r4 < 64; r4 += 4) {
            ulonglong2 uq[4], mq[4];
#pragma unroll
            for (int tt = 0; tt < 4; tt++) uq[tt] = ld2u64(&sA[(t0 + tt) * 68 + r4]);
#pragma unroll
            for (int j = 0; j < 4; j++)  mq[j]  = ld2u64(&sMT[(oc4 + j) * 68 + r4]);
#pragma unroll
            for (int tt = 0; tt < 4; tt++)
#pragma unroll
                for (int j = 0; j < 4; j++) {
                    FMA2(oacc2[tt][j], uq[tt].x, mq[j].x);
                    FMA2(oacc2[tt][j], uq[tt].y, mq[j].y);
                }
        }
    }

#pragma unroll
    for (int tt = 0; tt < 4; tt++)
        st4(&out[(base + t0 + tt) * 64 + oc4],
            make_float4(unpack_sum(oacc2[tt][0]), unpack_sum(oacc2[tt][1]),
                        unpack_sum(oacc2[tt][2]), unpack_sum(oacc2[tt][3])));
}

// ---------------------------------------------------------------------------
extern "C" void kernel_launch(void* const* d_in, const int* in_sizes, int n_in,
                              void* d_out, int out_size) {
    const float* x   = (const float*)d_in[0];
    const float* pos = (const float*)d_in[1];
    const float* Wq  = (const float*)d_in[2];
    const float* Wk  = (const float*)d_in[3];
    const float* Wv  = (const float*)d_in[4];
    const float* Wo  = (const float*)d_in[5];
    float* out = (float*)d_out;

    cudaFuncSetAttribute(kv_kernel,  cudaFuncAttributeMaxDynamicSharedMemorySize,
                         KV_SMEM_FLOATS * (int)sizeof(float));
    cudaFuncSetAttribute(out_kernel, cudaFuncAttributeMaxDynamicSharedMemorySize,
                         OUT_SMEM_FLOATS * (int)sizeof(float));

    cs_kernel<<<(BB * NN * 32 + 255) / 256, 256>>>(pos);
    kv_kernel<<<dim3(32, HH, BB), 256, KV_SMEM_FLOATS * sizeof(float)>>>(x, Wk, Wv);
    m_kernel<<<dim3(HH, BB), 256>>>(Wo);
    out_kernel<<<dim3(NN / 64, BB), 256, OUT_SMEM_FLOATS * sizeof(float)>>>(x, Wq, out);
}

// round 15
// speedup vs baseline: 2.2854x; 2.2817x over previous
#include <cuda_runtime.h>
#include <cuda_bf16.h>
#include <mma.h>
#include <math.h>
#include <stdint.h>

using namespace nvcuda;

// Problem constants
#define BB 4
#define NN 16384
#define DD 64
#define HH 8

// scratch (static __device__ globals: allocation-free per harness rules)
__device__ float g_cs [BB * NN * 64];            // per token: cos[0..31], sin[0..31]
__device__ float g_kvp[BB * HH * 32 * 4096];     // per-(b,h,slab) partial kv
__device__ float g_M  [BB * HH * 4096];          // (kv @ Wo_h)/N, [d][o]

__device__ __forceinline__ float4 ld4(const float* p) { return *reinterpret_cast<const float4*>(p); }
__device__ __forceinline__ void   st4(float* p, float4 v) { *reinterpret_cast<float4*>(p) = v; }
__device__ __forceinline__ void split_bf16(float v, __nv_bfloat16& h, __nv_bfloat16& l) {
    h = __float2bfloat16(v);
    l = __float2bfloat16(v - __bfloat162float(h));
}
__device__ __forceinline__ void st_bf2(__nv_bfloat16* p, __nv_bfloat16 a, __nv_bfloat16 b) {
    __nv_bfloat162 v; v.x = a; v.y = b;
    *reinterpret_cast<__nv_bfloat162*>(p) = v;
}

typedef wmma::fragment<wmma::matrix_a, 16, 16, 16, __nv_bfloat16, wmma::row_major> FragA;
typedef wmma::fragment<wmma::matrix_b, 16, 16, 16, __nv_bfloat16, wmma::col_major> FragBc;
typedef wmma::fragment<wmma::matrix_b, 16, 16, 16, __nv_bfloat16, wmma::row_major> FragBr;
typedef wmma::fragment<wmma::accumulator, 16, 16, 16, float> FragC;

// ---------------------------------------------------------------------------
// K0: cos/sin table (token-major, as in R3).  f_j = pos*64*10000^(-j/32)
// ---------------------------------------------------------------------------
__global__ void cs_kernel(const float* __restrict__ pos) {
    int idx = blockIdx.x * blockDim.x + threadIdx.x;
    if (idx >= BB * NN * 32) return;
    int j = idx & 31;
    int n = idx >> 5;
    float t = pos[n] * 64.0f;
    float inv = expf(-0.28782313662425572f * (float)j);  // 10000^(-j/32)
    float f = t * inv;
    g_cs[n * 64 + j]      = cosf(f);
    g_cs[n * 64 + 32 + j] = sinf(f);
}

// ---------------------------------------------------------------------------
// K1 (proven R3 SIMT): per-(b,h,slab) kproj+vproj -> LN -> RoPE(k) -> kv partial
// ---------------------------------------------------------------------------
#define KV_SMEM_FLOATS (8192 + 8704)
__global__ __launch_bounds__(256, 3)
void kv_kernel(const float* __restrict__ x, const float* __restrict__ Wk,
               const float* __restrict__ Wv) {
    extern __shared__ float sm[];
    float* sW  = sm;                    // [64][128] : cols 0..63 = Wk_h, 64..127 = Wv_h
    float* sU  = sm + 8192;             // union region (8704 floats)
    float* sXT = sU;                    // [64][68]  : x transposed (i, t)
    float* sCS = sU + 4352;             // [64][68]  : (t, cos|sin)
    float* sKV = sU;                    // [64][132] : ALIASED, live only in P2

    const int s = blockIdx.x, h = blockIdx.y, b = blockIdx.z;
    const int tid  = threadIdx.x;
    const int trow = tid >> 4, ocol = tid & 15;
    const int t0  = trow << 2;
    const int oc4 = ocol << 2;
    const int jb  = (ocol & 7) << 2;
    const float sgn = (ocol < 8) ? -1.0f : 1.0f;

    for (int idx = tid; idx < 4096; idx += 256) {
        int i = idx >> 6, o = idx & 63;
        int g = i * 512 + h * 64 + o;
        sW[i * 128 + o]      = Wk[g];
        sW[i * 128 + 64 + o] = Wv[g];
    }

    float kv[4][4];
#pragma unroll
    for (int a = 0; a < 4; a++)
#pragma unroll
        for (int e = 0; e < 4; e++) kv[a][e] = 0.0f;

    for (int c = 0; c < 8; c++) {
        const size_t base = (size_t)b * NN + (size_t)s * 512 + (size_t)c * 64;

        for (int idx = tid; idx < 4096; idx += 256) {
            int t = idx >> 6, i = idx & 63;
            sXT[i * 68 + t] = x[(base + t) * 64 + i];
            sCS[t * 68 + i] = g_cs[(base + t) * 64 + i];
        }
        __syncthreads();

        float ak[4][4], av[4][4];
#pragma unroll
        for (int a = 0; a < 4; a++)
#pragma unroll
            for (int e = 0; e < 4; e++) { ak[a][e] = 0.0f; av[a][e] = 0.0f; }

#pragma unroll 8
        for (int i = 0; i < 64; i++) {
            float4 xv = ld4(&sXT[i * 68 + t0]);
            float4 wk = ld4(&sW[i * 128 + oc4]);
            float4 wv = ld4(&sW[i * 128 + 64 + oc4]);
            float xs[4] = {xv.x, xv.y, xv.z, xv.w};
            float ks[4] = {wk.x, wk.y, wk.z, wk.w};
            float vs[4] = {wv.x, wv.y, wv.z, wv.w};
#pragma unroll
            for (int tt = 0; tt < 4; tt++)
#pragma unroll
                for (int j = 0; j < 4; j++) {
                    ak[tt][j] = fmaf(xs[tt], ks[j], ak[tt][j]);
                    av[tt][j] = fmaf(xs[tt], vs[j], av[tt][j]);
                }
        }

        const float inv64 = 1.0f / 64.0f;
#pragma unroll
        for (int tt = 0; tt < 4; tt++) {
            float sk = ak[tt][0] + ak[tt][1] + ak[tt][2] + ak[tt][3];
            float sk2 = ak[tt][0]*ak[tt][0] + ak[tt][1]*ak[tt][1] + ak[tt][2]*ak[tt][2] + ak[tt][3]*ak[tt][3];
            float sv = av[tt][0] + av[tt][1] + av[tt][2] + av[tt][3];
            float sv2 = av[tt][0]*av[tt][0] + av[tt][1]*av[tt][1] + av[tt][2]*av[tt][2] + av[tt][3]*av[tt][3];
#pragma unroll
            for (int m = 1; m <= 8; m <<= 1) {
                sk  += __shfl_xor_sync(0xffffffffu, sk,  m);
                sk2 += __shfl_xor_sync(0xffffffffu, sk2, m);
                sv  += __shfl_xor_sync(0xffffffffu, sv,  m);
                sv2 += __shfl_xor_sync(0xffffffffu, sv2, m);
            }
            float mk = sk * inv64;
            float vk = fmaxf(sk2 * inv64 - mk * mk, 0.0f);
            float rk = rsqrtf(vk + 1e-5f);
            float mv = sv * inv64;
            float vv = fmaxf(sv2 * inv64 - mv * mv, 0.0f);
            float rv = rsqrtf(vv + 1e-5f);

            float kn[4];
#pragma unroll
            for (int j = 0; j < 4; j++) {
                kn[j]     = (ak[tt][j] - mk) * rk;
                av[tt][j] = (av[tt][j] - mv) * rv;
            }
            float pk[4];
#pragma unroll
            for (int j = 0; j < 4; j++)
                pk[j] = __shfl_xor_sync(0xffffffffu, kn[j], 8);

            int t = t0 + tt;
            float4 cq = ld4(&sCS[t * 68 + jb]);
            float4 sq = ld4(&sCS[t * 68 + 32 + jb]);
            float cs[4] = {cq.x, cq.y, cq.z, cq.w};
            float ss[4] = {sq.x, sq.y, sq.z, sq.w};
#pragma unroll
            for (int j = 0; j < 4; j++)
                ak[tt][j] = kn[j] * cs[j] + sgn * pk[j] * ss[j];
        }
        __syncthreads();

#pragma unroll
        for (int tt = 0; tt < 4; tt++) {
            int t = t0 + tt;
            st4(&sKV[t * 132 + oc4],      make_float4(ak[tt][0], ak[tt][1], ak[tt][2], ak[tt][3]));
            st4(&sKV[t * 132 + 64 + oc4], make_float4(av[tt][0], av[tt][1], av[tt][2], av[tt][3]));
        }
        __syncthreads();

#pragma unroll 4
        for (int t = 0; t < 64; t++) {
            float4 kq = ld4(&sKV[t * 132 + t0]);
            float4 vq = ld4(&sKV[t * 132 + 64 + oc4]);
            float kd[4] = {kq.x, kq.y, kq.z, kq.w};
            float ve[4] = {vq.x, vq.y, vq.z, vq.w};
#pragma unroll
            for (int a = 0; a < 4; a++)
#pragma unroll
                for (int e = 0; e < 4; e++)
                    kv[a][e] = fmaf(kd[a], ve[e], kv[a][e]);
        }
        __syncthreads();
    }

    float* dst = g_kvp + ((((size_t)b * HH + h) * 32 + s) << 12);
#pragma unroll
    for (int a = 0; a < 4; a++)
        st4(&dst[(t0 + a) * 64 + oc4], make_float4(kv[a][0], kv[a][1], kv[a][2], kv[a][3]));
}

// ---------------------------------------------------------------------------
// K2 (proven R3): reduce 32 slabs -> kv[b,h];  M = kv @ Wo_h / N, [d][o]
// ---------------------------------------------------------------------------
__global__ void m_kernel(const float* __restrict__ Wo) {
    __shared__ float sKv[64 * 68];
    __shared__ float sWo[64 * 68];
    const int h = blockIdx.x, b = blockIdx.y;
    const int tid = threadIdx.x;

    const float* p0 = g_kvp + (((size_t)b * HH + h) * 32 << 12);
    for (int idx = tid; idx < 4096; idx += 256) {
        float acc = 0.0f;
#pragma unroll 8
        for (int s = 0; s < 32; s++) acc += p0[(size_t)s * 4096 + idx];
        int d = idx >> 6, e = idx & 63;
        sKv[d * 68 + e] = acc;
        sWo[d * 68 + e] = Wo[(h * 64 + d) * 64 + e];
    }
    __syncthreads();

    const int d0 = (tid >> 4) << 2, o0 = (tid & 15) << 2;
    float m[4][4];
#pragma unroll
    for (int a = 0; a < 4; a++)
#pragma unroll
        for (int e = 0; e < 4; e++) m[a][e] = 0.0f;

#pragma unroll 4
    for (int e = 0; e < 64; e++) {
        float kd[4];
#pragma unroll
        for (int a = 0; a < 4; a++) kd[a] = sKv[(d0 + a) * 68 + e];
        float4 wq = ld4(&sWo[e * 68 + o0]);
        float wo[4] = {wq.x, wq.y, wq.z, wq.w};
#pragma unroll
        for (int a = 0; a < 4; a++)
#pragma unroll
            for (int j = 0; j < 4; j++) m[a][j] = fmaf(kd[a], wo[j], m[a][j]);
    }

    const float scale = 1.0f / (float)NN;
    float* dst = g_M + ((size_t)b * HH + h) * 4096;
#pragma unroll
    for (int a = 0; a < 4; a++)
        st4(&dst[(d0 + a) * 64 + o0],
            make_float4(m[a][0] * scale, m[a][1] * scale, m[a][2] * scale, m[a][3] * scale));
}

// ---------------------------------------------------------------------------
// K3: wmma bf16-split out kernel.  Block = 64 tokens, 128 threads (4 warps).
//  per head: GEMM1 C[64 t][64 o] = Xsplit @ Wq_h^T split (3 K64 segs, col-major B)
//            RoPE epilogue (64 threads), split-store U (aliased over Wq tile)
//            GEMM2 dout += Usplit @ M_h split (row-major B), frag-resident
// smem bytes: sX 17408 | sWU 17408 (union Wq/U) | sCS 17408 | sC 17408
//             | sMh 9216 | sMl 9216  = 88064
// ---------------------------------------------------------------------------
#define OUT_SX_OFF   0
#define OUT_SWU_OFF  17408
#define OUT_SCS_OFF  34816
#define OUT_SC_OFF   52224
#define OUT_SMH_OFF  69632
#define OUT_SML_OFF  78848
#define OUT_SMEM_BYTES 88064

__global__ __launch_bounds__(128)
void out_kernel(const float* __restrict__ x, const float* __restrict__ Wq,
                float* __restrict__ out) {
    extern __shared__ char smc[];
    __nv_bfloat16* sX  = (__nv_bfloat16*)(smc + OUT_SX_OFF);   // [64][136] t-major, cols 0-63 hi(i) | 64-127 lo(i)
    __nv_bfloat16* sWU = (__nv_bfloat16*)(smc + OUT_SWU_OFF);  // [64][136] union: Wq^T(o,i) split | U(t,r) split
    float*         sCS = (float*)(smc + OUT_SCS_OFF);          // [64][68]
    float*         sC  = (float*)(smc + OUT_SC_OFF);           // [64][68]
    __nv_bfloat16* sMh = (__nv_bfloat16*)(smc + OUT_SMH_OFF);  // [64][72]
    __nv_bfloat16* sMl = (__nv_bfloat16*)(smc + OUT_SML_OFF);  // [64][72]

    const int tid = threadIdx.x, wid = tid >> 5;
    const int chunk = blockIdx.x, b = blockIdx.y;
    const size_t base = (size_t)b * NN + (size_t)chunk * 64;
    const int mA = wid * 16;

    // stage X split + cos/sin (once per block)
    for (int p = tid; p < 2048; p += 128) {
        int t = p >> 5, i2 = (p & 31) << 1;
        float2 xv = *reinterpret_cast<const float2*>(x + (base + t) * 64 + i2);
        __nv_bfloat16 h0, l0, h1, l1;
        split_bf16(xv.x, h0, l0);  split_bf16(xv.y, h1, l1);
        st_bf2(sX + t * 136 + i2,      h0, h1);
        st_bf2(sX + t * 136 + 64 + i2, l0, l1);
    }
    for (int idx = tid; idx < 4096; idx += 128) {
        int t = idx >> 6, i = idx & 63;
        sCS[t * 68 + i] = g_cs[(base + t) * 64 + i];
    }

    FragC dout[4];
#pragma unroll
    for (int nt = 0; nt < 4; nt++) wmma::fill_fragment(dout[nt], 0.0f);

    for (int h = 0; h < HH; h++) {
        __syncthreads();   // prior GEMM2 reads of sWU(U)/sM done before overwrite

        for (int idx = tid; idx < 4096; idx += 128) {
            int i = idx >> 6, o = idx & 63;
            __nv_bfloat16 hh, ll;
            split_bf16(Wq[i * 512 + h * 64 + o], hh, ll);
            sWU[o * 136 + i] = hh;  sWU[o * 136 + 64 + i] = ll;
        }
        for (int idx = tid; idx < 4096; idx += 128) {
            int d = idx >> 6, o = idx & 63;
            __nv_bfloat16 hh, ll;
            split_bf16(g_M[(((size_t)b * HH + h) * 64 + d) * 64 + o], hh, ll);
            sMh[d * 72 + o] = hh;  sMl[d * 72 + o] = ll;
        }
        __syncthreads();

        // GEMM1: C = Xhi@Whi + Xlo@Whi + Xhi@Wlo   (B col-major: rows = o)
        {
            FragC cf[4];
#pragma unroll
            for (int nt = 0; nt < 4; nt++) wmma::fill_fragment(cf[nt], 0.0f);
#pragma unroll
            for (int seg = 0; seg < 3; seg++) {
                const __nv_bfloat16* aB = sX + mA * 136 + ((seg == 1) ? 64 : 0);
                const __nv_bfloat16* bB = sWU + ((seg == 2) ? 64 : 0);
#pragma unroll
                for (int k = 0; k < 64; k += 16) {
                    FragA af;
                    wmma::load_matrix_sync(af, aB + k, 136);
#pragma unroll
                    for (int nt = 0; nt < 4; nt++) {
                        FragBc bf;
                        wmma::load_matrix_sync(bf, bB + nt * 16 * 136 + k, 136);
                        wmma::mma_sync(cf[nt], af, bf, cf[nt]);
                    }
                }
            }
#pragma unroll
            for (int nt = 0; nt < 4; nt++)
                wmma::store_matrix_sync(sC + mA * 68 + nt * 16, cf[nt], 68, wmma::mem_row_major);
        }
        __syncthreads();   // GEMM1 done reading sWU; sC complete

        // RoPE epilogue: thread t<64 -> token t; split-store U over sWU
        if (tid < 64) {
            const int t = tid;
            float q[64];
#pragma unroll
            for (int j = 0; j < 64; j++) q[j] = sC[t * 68 + j];
#pragma unroll
            for (int j = 0; j < 32; j++) {
                float cc = sCS[t * 68 + j];
                float sn = sCS[t * 68 + 32 + j];
                float u0 = q[j] * cc - q[j + 32] * sn;
                float u1 = q[j + 32] * cc + q[j] * sn;
                __nv_bfloat16 hh, ll;
                split_bf16(u0, hh, ll);
                sWU[t * 136 + j] = hh;       sWU[t * 136 + 64 + j] = ll;
                split_bf16(u1, hh, ll);
                sWU[t * 136 + j + 32] = hh;  sWU[t * 136 + 96 + j] = ll;
            }
        }
        __syncthreads();

        // GEMM2: dout += Uhi@Mhi + Ulo@Mhi + Uhi@Mlo   (B row-major: rows = d)
#pragma unroll
        for (int seg = 0; seg < 3; seg++) {
            const __nv_bfloat16* aB = sWU + mA * 136 + ((seg == 1) ? 64 : 0);
            const __nv_bfloat16* bB = (seg == 2) ? sMl : sMh;
#pragma unroll
            for (int k = 0; k < 64; k += 16) {
                FragA af;
                wmma::load_matrix_sync(af, aB + k, 136);
#pragma unroll
                for (int nt = 0; nt < 4; nt++) {
                    FragBr bf;
                    wmma::load_matrix_sync(bf, bB + k * 72 + nt * 16, 72);
                    wmma::mma_sync(dout[nt], af, bf, dout[nt]);
                }
            }
        }
    }

    __syncthreads();
#pragma unroll
    for (int nt = 0; nt < 4; nt++)
        wmma::store_matrix_sync(sC + mA * 68 + nt * 16, dout[nt], 68, wmma::mem_row_major);
    __syncthreads();
    for (int idx = tid; idx < 4096; idx += 128) {
        int t = idx >> 6, o = idx & 63;
        out[(base + t) * 64 + o] = sC[t * 68 + o];
    }
}

// ---------------------------------------------------------------------------
extern "C" void kernel_launch(void* const* d_in, const int* in_sizes, int n_in,
                              void* d_out, int out_size) {
    const float* x   = (const float*)d_in[0];
    const float* pos = (const float*)d_in[1];
    const float* Wq  = (const float*)d_in[2];
    const float* Wk  = (const float*)d_in[3];
    const float* Wv  = (const float*)d_in[4];
    const float* Wo  = (const float*)d_in[5];
    float* out = (float*)d_out;

    cudaFuncSetAttribute(kv_kernel,  cudaFuncAttributeMaxDynamicSharedMemorySize,
                         KV_SMEM_FLOATS * (int)sizeof(float));
    cudaFuncSetAttribute(out_kernel, cudaFuncAttributeMaxDynamicSharedMemorySize, OUT_SMEM_BYTES);

    cs_kernel<<<(BB * NN * 32 + 255) / 256, 256>>>(pos);
    kv_kernel<<<dim3(32, HH, BB), 256, KV_SMEM_FLOATS * sizeof(float)>>>(x, Wk, Wv);
    m_kernel<<<dim3(HH, BB), 256>>>(Wo);
    out_kernel<<<dim3(NN / 64, BB), 128, OUT_SMEM_BYTES>>>(x, Wq, out);
}